// round 7
// baseline (speedup 1.0000x reference)
#include <cuda_runtime.h>
#include <cstdint>
#include <cstddef>

#define S 8192
#define M 2048
#define E 64

#define KC 32
#define APAD 66
#define TOKB 64                     // tokens per compute block
#define NCOMPUTE (S / TOKB)         // 128
#define NZERO 160
#define NCHUNK (S / 32)             // 256

// dynamic smem layout (bytes)
#define SM_AS_BYTES (2 * KC * APAD * 4)      // 16896
#define SM_BS_BYTES (2 * KC * 64 * 8)        // 32768
#define SM_TOTAL    (SM_AS_BYTES + SM_BS_BYTES)  // 49664

typedef unsigned long long u64;

// Scratch (device globals — no allocations allowed)
__device__ float g_bt[(size_t)M * E];        // B transposed [k][e], 512 KB
__device__ float g_colsum[E];
__device__ int   g_expert[S];
__device__ float g_gate[S];
__device__ int   g_rank[S];
__device__ int   g_wcount[NCHUNK * E];
__device__ int   g_base[NCHUNK * E];

__device__ __forceinline__ u64 pack2(float x) {
    u64 r;
    asm("mov.b64 %0, {%1, %1};" : "=l"(r) : "f"(x));
    return r;
}
__device__ __forceinline__ void ffma2(u64 &d, u64 a, u64 b) {
    asm("fma.rn.f32x2 %0, %1, %2, %0;" : "+l"(d) : "l"(a), "l"(b));
}

// ---------------------------------------------------------------------------
// init: zero chunk histograms + colsum; transpose B -> g_bt[k][e]
// ---------------------------------------------------------------------------
__global__ void init_kernel(const float* __restrict__ wgt) {
    int i = blockIdx.x * blockDim.x + threadIdx.x;
    int nth = gridDim.x * blockDim.x;
    int4* w4 = (int4*)g_wcount;
    const int nw4 = (NCHUNK * E) / 4;                // 4096
    for (int j = i; j < nw4; j += nth) w4[j] = make_int4(0, 0, 0, 0);
    if (i < E) g_colsum[i] = 0.f;
    // transpose: read wgt[e][k] coalesced (k-contig), write g_bt[k][e]
    for (int j = i; j < M * E; j += nth) {
        int e = j >> 11;            // j / 2048
        int k = j & (M - 1);
        g_bt[(size_t)k * E + e] = wgt[j];
    }
}

// ---------------------------------------------------------------------------
// Fused kernel:
//   blocks [0, NCOMPUTE): GEMM (64 tokens x 64 experts x K=2048) with fused
//     softmax/argmax/rank/colsum epilogue.
//   blocks [NCOMPUTE, NCOMPUTE+NZERO): zero the entire output buffer.
// 2 blocks/SM co-resident -> zero stores overlap GEMM compute.
// ---------------------------------------------------------------------------
__global__ void __launch_bounds__(256, 2)
fused_gemm_zero(const float* __restrict__ in,
                float* __restrict__ out,
                size_t out_elems) {
    const int bid = blockIdx.x;
    const int tid = threadIdx.x;

    if (bid >= NCOMPUTE) {
        // ---- zero role ----
        const int zid = bid - NCOMPUTE;
        const size_t total4 = out_elems >> 2;
        float4 z = make_float4(0.f, 0.f, 0.f, 0.f);
        float4* o4 = (float4*)out;
        for (size_t i = (size_t)zid * 256 + tid; i < total4;
             i += (size_t)NZERO * 256)
            __stcs(o4 + i, z);
        if (zid == 0 && tid == 0) {
            for (size_t r = total4 * 4; r < out_elems; ++r)
                __stcs(out + r, 0.f);
        }
        return;
    }

    // ---- compute role ----
    extern __shared__ char smraw[];
    float* As = (float*)smraw;                       // [2][KC*APAD]
    u64*   Bs = (u64*)(smraw + SM_AS_BYTES);         // [2][KC*64]
    // epilogue overlay (over Bs region)
    float* Lsm  = (float*)(smraw + SM_AS_BYTES);     // [64][65]
    float* mxA  = Lsm + 64 * 65;
    float* invA = mxA + 64;

    const int w = tid >> 5;          // warp 0..7 -> experts 8w..8w+7
    const int l = tid & 31;          // lane -> tokens 2l, 2l+1
    const int s0 = bid * TOKB;

    // loader indices
    const int a_t0 = tid >> 3;       // A: token for idx=tid       (0..31)
    const int a_q  = tid & 7;        //    float4 col
    const int b_k0 = tid >> 4;       // B: k for idx=tid           (0..15)
    const int b_e4 = tid & 15;       //    float4 col within row

    u64 acc[8];
#pragma unroll
    for (int j = 0; j < 8; ++j) acc[j] = 0ull;

    float4 ra0, ra1, rb0, rb1;

#define LDGC(c)                                                              \
    {                                                                        \
        int k0 = (c) * KC;                                                   \
        ra0 = __ldcs((const float4*)(in + (size_t)(s0 + a_t0) * M + k0 + a_q * 4));      \
        ra1 = __ldcs((const float4*)(in + (size_t)(s0 + a_t0 + 32) * M + k0 + a_q * 4)); \
        rb0 = *(const float4*)(g_bt + (size_t)(k0 + b_k0) * E + b_e4 * 4);   \
        rb1 = *(const float4*)(g_bt + (size_t)(k0 + b_k0 + 16) * E + b_e4 * 4); \
    }

#define STSC(buf)                                                            \
    {                                                                        \
        float* ab = As + (buf) * (KC * APAD);                                \
        ab[(a_q * 4 + 0) * APAD + a_t0] = ra0.x;                             \
        ab[(a_q * 4 + 1) * APAD + a_t0] = ra0.y;                             \
        ab[(a_q * 4 + 2) * APAD + a_t0] = ra0.z;                             \
        ab[(a_q * 4 + 3) * APAD + a_t0] = ra0.w;                             \
        ab[(a_q * 4 + 0) * APAD + a_t0 + 32] = ra1.x;                        \
        ab[(a_q * 4 + 1) * APAD + a_t0 + 32] = ra1.y;                        \
        ab[(a_q * 4 + 2) * APAD + a_t0 + 32] = ra1.z;                        \
        ab[(a_q * 4 + 3) * APAD + a_t0 + 32] = ra1.w;                        \
        u64* bb = Bs + (buf) * (KC * 64);                                    \
        bb[b_k0 * 64 + b_e4 * 4 + 0] = pack2(rb0.x);                         \
        bb[b_k0 * 64 + b_e4 * 4 + 1] = pack2(rb0.y);                         \
        bb[b_k0 * 64 + b_e4 * 4 + 2] = pack2(rb0.z);                         \
        bb[b_k0 * 64 + b_e4 * 4 + 3] = pack2(rb0.w);                         \
        bb[(b_k0 + 16) * 64 + b_e4 * 4 + 0] = pack2(rb1.x);                  \
        bb[(b_k0 + 16) * 64 + b_e4 * 4 + 1] = pack2(rb1.y);                  \
        bb[(b_k0 + 16) * 64 + b_e4 * 4 + 2] = pack2(rb1.z);                  \
        bb[(b_k0 + 16) * 64 + b_e4 * 4 + 3] = pack2(rb1.w);                  \
    }

    LDGC(0);
    STSC(0);
    __syncthreads();

    const int NCHUNKS_K = M / KC;    // 64
    for (int c = 0; c < NCHUNKS_K; ++c) {
        if (c + 1 < NCHUNKS_K) LDGC(c + 1);

        const float* a_ = As + (c & 1) * (KC * APAD);
        const u64*   b_ = Bs + (c & 1) * (KC * 64);
#pragma unroll
        for (int kk = 0; kk < KC; ++kk) {
            u64 av = *(const u64*)(a_ + kk * APAD + 2 * l);
            const ulonglong2* brow =
                (const ulonglong2*)(b_ + kk * 64 + w * 8);
            ulonglong2 b01 = brow[0];
            ulonglong2 b23 = brow[1];
            ulonglong2 b45 = brow[2];
            ulonglong2 b67 = brow[3];
            ffma2(acc[0], b01.x, av);
            ffma2(acc[1], b01.y, av);
            ffma2(acc[2], b23.x, av);
            ffma2(acc[3], b23.y, av);
            ffma2(acc[4], b45.x, av);
            ffma2(acc[5], b45.y, av);
            ffma2(acc[6], b67.x, av);
            ffma2(acc[7], b67.y, av);
        }
        __syncthreads();
        if (c + 1 < NCHUNKS_K) {
            STSC((c + 1) & 1);
            __syncthreads();
        }
    }
#undef LDGC
#undef STSC

    // ---- epilogue: logits tile -> smem ----
#pragma unroll
    for (int j = 0; j < 8; ++j) {
        float2 v = *(float2*)&acc[j];
        Lsm[(2 * l) * 65 + 8 * w + j]     = v.x;   // token 2l
        Lsm[(2 * l + 1) * 65 + 8 * w + j] = v.y;   // token 2l+1
    }
    __syncthreads();

    // softmax + argmax + rank/wcount (threads 0..63 = one token each)
    if (tid < 64) {
        const int t = tid;
        const float* row = Lsm + t * 65;
        float mx = row[0];
        int am = 0;
#pragma unroll
        for (int e = 1; e < E; ++e) {
            float v = row[e];
            if (v > mx) { mx = v; am = e; }   // strict > keeps first max
        }
        float sum = 0.f;
#pragma unroll
        for (int e = 0; e < E; ++e) sum += __expf(row[e] - mx);
        float inv = 1.f / sum;

        const int s = s0 + t;
        g_expert[s] = am;
        g_gate[s]   = inv;                    // gate at argmax
        mxA[t]  = mx;
        invA[t] = inv;

        // rank within 32-token chunk (token order == lane order)
        unsigned grp = __match_any_sync(0xffffffffu, am);
        int lane = t & 31;
        int rank = __popc(grp & ((1u << lane) - 1u));
        g_rank[s] = rank;
        if (rank == 0) g_wcount[(s >> 5) * E + am] = __popc(grp);
    }
    __syncthreads();

    // colsum of full softmax gates (for l_aux)
    {
        const int e = tid & 63;
        const int g = tid >> 6;               // 0..3, 16 tokens each
        float part = 0.f;
#pragma unroll 4
        for (int t = g * 16; t < g * 16 + 16; ++t)
            part += __expf(Lsm[t * 65 + e] - mxA[t]) * invA[t];
        atomicAdd(&g_colsum[e], part);
    }
}

// ---------------------------------------------------------------------------
// Per-expert exclusive prefix over the 256 chunk counts (one block/expert),
// plus exp_counts and l_aux (counts are pre-capacity, matching reference).
// ---------------------------------------------------------------------------
__global__ void base_kernel(float* __restrict__ out, size_t SEC) {
    const int e = blockIdx.x;
    const int c = threadIdx.x;          // chunk 0..255
    const int lane = c & 31, w = c >> 5;

    int v = g_wcount[c * E + e];
    int x = v;
#pragma unroll
    for (int d = 1; d < 32; d <<= 1) {
        int t = __shfl_up_sync(0xffffffffu, x, d);
        if (lane >= d) x += t;
    }
    __shared__ int wsum[8];
    if (lane == 31) wsum[w] = x;
    __syncthreads();
    if (c == 0) {
        int a = 0;
#pragma unroll
        for (int i = 0; i < 8; ++i) { int t = wsum[i]; wsum[i] = a; a += t; }
    }
    __syncthreads();
    int excl = x - v + wsum[w];
    g_base[c * E + e] = excl;

    if (c == 255) {
        int tot = excl + v;
        out[1 + 2 * SEC + e] = (float)tot;        // exp_counts
        float term = g_colsum[e] * (float)tot *
                     ((float)E / ((float)S * (float)S));
        atomicAdd(out, term);                     // l_aux
    }
}

// ---------------------------------------------------------------------------
// Scatter the <= S nonzeros into the (already-zeroed) output.
// ---------------------------------------------------------------------------
__global__ void scatter_kernel(float* __restrict__ out, size_t SEC, int CAPV) {
    const int s = blockIdx.x * 256 + threadIdx.x;
    const int e = g_expert[s];
    const int pos = g_base[(s >> 5) * E + e] + g_rank[s];
    if (pos < CAPV) {
        size_t o = 1 + ((size_t)s * E + e) * (size_t)CAPV + pos;
        out[o]       = g_gate[s];   // combine_weights
        out[o + SEC] = 1.0f;        // dispatch_mask
    }
}

// ---------------------------------------------------------------------------
extern "C" void kernel_launch(void* const* d_in, const int* in_sizes, int n_in,
                              void* d_out, int out_size) {
    const float* in  = (const float*)d_in[0];
    const float* wgt = (const float*)d_in[1];
    float* out = (float*)d_out;

    // Derive capacity from out_size; fall back to the analytic value (128).
    long long c = ((long long)out_size - 1 - E) / (2LL * S * E);
    int CAPV = 128;
    if (c > 0 && (1 + 2LL * S * E * c + E) == (long long)out_size)
        CAPV = (int)c;
    size_t SEC = (size_t)S * E * (size_t)CAPV;

    cudaFuncSetAttribute(fused_gemm_zero,
                         cudaFuncAttributeMaxDynamicSharedMemorySize,
                         SM_TOTAL);

    init_kernel<<<128, 256>>>(wgt);
    fused_gemm_zero<<<NCOMPUTE + NZERO, 256, SM_TOTAL>>>(in, out,
                                                         (size_t)out_size);
    base_kernel<<<E, 256>>>(out, SEC);
    scatter_kernel<<<S / 256, 256>>>(out, SEC, CAPV);
}

// round 8
// speedup vs baseline: 1.0880x; 1.0880x over previous
#include <cuda_runtime.h>
#include <cstdint>
#include <cstddef>

// Problem shape (fixed by the dataset)
#define S 8192
#define M 2048
#define E 64

#define KSPLIT 4
#define KSLICE (M / KSPLIT)      // 512
#define KC 32
#define TOKB 256                 // tokens per compute block
#define NCOMPUTE ((S / TOKB) * KSPLIT)   // 32 * 4 = 128
#define NZERO 168                // 128 + 168 = 296 = 2 * 148 SMs
#define NCHUNK (S / 32)          // 256 warp-sized token chunks

#define TILE4 4096               // float4s per zero tile (64 KB)

typedef unsigned long long u64;

// Scratch (device globals — no allocations allowed)
__device__ float    g_logits[(size_t)S * E];   // 2 MB: split-K accumulator
__device__ float    g_colsum[E];
__device__ int      g_expert[S];
__device__ float    g_gate[S];
__device__ int      g_rank[S];
__device__ int      g_wcount[NCHUNK * E];
__device__ int      g_base[NCHUNK * E];
__device__ unsigned g_ticket;

__device__ __forceinline__ u64 pack2(float x) {
    u64 r;
    asm("mov.b64 %0, {%1, %1};" : "=l"(r) : "f"(x));
    return r;
}
__device__ __forceinline__ void ffma2(u64 &d, u64 a, u64 b) {
    asm("fma.rn.f32x2 %0, %1, %2, %0;" : "+l"(d) : "l"(a), "l"(b));
}

// ---------------------------------------------------------------------------
// Warp-level work-stolen zeroing: grab 64KB tiles off a global ticket and
// stream float4 zeros. Idempotent -> deterministic output regardless of
// which warp zeroes which tile.
// ---------------------------------------------------------------------------
__device__ __forceinline__ void zero_pool(float4* o4, size_t total4, int lane) {
    const float4 z = make_float4(0.f, 0.f, 0.f, 0.f);
    for (;;) {
        unsigned t = 0;
        if (lane == 0) t = atomicAdd(&g_ticket, 1u);
        t = __shfl_sync(0xffffffffu, t, 0);
        size_t b = (size_t)t * TILE4;
        if (b >= total4) return;
        if (b + TILE4 <= total4) {
#pragma unroll 8
            for (int j = lane; j < TILE4; j += 32)
                __stcs(o4 + b + j, z);
        } else {
            for (size_t j = b + lane; j < total4; j += 32)
                __stcs(o4 + j, z);
        }
    }
}

// ---------------------------------------------------------------------------
// init: zero split-K logits accumulator, colsum, histograms, ticket
// ---------------------------------------------------------------------------
__global__ void init_kernel() {
    int i = blockIdx.x * blockDim.x + threadIdx.x;
    float4 z = make_float4(0.f, 0.f, 0.f, 0.f);
    float4* p = (float4*)g_logits;
    const int n4 = (S * E) / 4;   // 131072
    for (int j = i; j < n4; j += gridDim.x * blockDim.x) p[j] = z;
    int4* w4 = (int4*)g_wcount;
    const int nw4 = (NCHUNK * E) / 4;  // 4096
    for (int j = i; j < nw4; j += gridDim.x * blockDim.x)
        w4[j] = make_int4(0, 0, 0, 0);
    if (i < E) g_colsum[i] = 0.f;
    if (i == 0) g_ticket = 0u;
}

// ---------------------------------------------------------------------------
// Fused kernel: bids [0, NZERO) start zeroing immediately (low bids launch
// first); bids [NZERO, NZERO+NCOMPUTE) run the split-K GEMM, then JOIN the
// zeroing pool. 296 blocks = 2/SM, one wave, so GEMM and stores overlap and
// every SM contributes store-issue bandwidth once its GEMM drains.
// ---------------------------------------------------------------------------
__global__ void __launch_bounds__(256, 2)
fused_gemm_zero(const float* __restrict__ in,
                const float* __restrict__ wgt,
                float* __restrict__ out,
                size_t out_elems) {
    const int bid = blockIdx.x;
    const int tid = threadIdx.x;
    const int lane = tid & 31;
    const size_t total4 = out_elems >> 2;

    if (bid < NZERO) {
        if (bid == 0 && tid == 0) {   // tail elements (out_elems % 4)
            for (size_t r = total4 * 4; r < out_elems; ++r)
                __stcs(out + r, 0.f);
        }
        zero_pool((float4*)out, total4, lane);
        return;
    }

    // ---- compute role ----
    const int cid = bid - NZERO;
    const int tb  = cid & (S / TOKB - 1);   // token block 0..31
    const int ks  = cid / (S / TOKB);       // k-split 0..3
    const int s0  = tb * TOKB;
    const int k0  = ks * KSLICE;

    __shared__ float As[KC][TOKB + 1];   // [32][257], +1 pad
    __shared__ float Bs[KC][E];          // [32][64], read warp-uniform

    const int warp = tid >> 5;
    const int myTok = s0 + warp * 32 + lane;

    u64 acc[E / 2];
#pragma unroll
    for (int j = 0; j < E / 2; ++j) acc[j] = 0ull;

    const int a_tok = tid >> 3;   // 0..31 within a pass
    const int a_kq  = tid & 7;    // which float4 of the 32-k row

    for (int c = 0; c < KSLICE / KC; ++c) {
        const int kc = k0 + c * KC;
        // Load A chunk (256 tokens x 32 k), coalesced
#pragma unroll
        for (int p = 0; p < 8; ++p) {
            int t = p * 32 + a_tok;
            float4 v = *(const float4*)(in + (size_t)(s0 + t) * M + kc + a_kq * 4);
            As[a_kq * 4 + 0][t] = v.x;
            As[a_kq * 4 + 1][t] = v.y;
            As[a_kq * 4 + 2][t] = v.z;
            As[a_kq * 4 + 3][t] = v.w;
        }
        // Load B chunk (64 experts x 32 k)
#pragma unroll
        for (int r = 0; r < 2; ++r) {
            int q = tid * 2 + r;
            int e = q >> 3, kq = q & 7;
            float4 v = *(const float4*)(wgt + (size_t)e * M + kc + kq * 4);
            Bs[kq * 4 + 0][e] = v.x;
            Bs[kq * 4 + 1][e] = v.y;
            Bs[kq * 4 + 2][e] = v.z;
            Bs[kq * 4 + 3][e] = v.w;
        }
        __syncthreads();
#pragma unroll
        for (int kk = 0; kk < KC; ++kk) {
            float a = As[kk][tid & 255];
            u64 aa = pack2(a);
            const u64* brow = (const u64*)(&Bs[kk][0]);
#pragma unroll
            for (int j = 0; j < E / 2; ++j) ffma2(acc[j], aa, brow[j]);
        }
        __syncthreads();
    }

    // Accumulate partial logits (split-K)
    float* lrow = g_logits + (size_t)myTok * E;
#pragma unroll
    for (int j = 0; j < E / 2; ++j) {
        float2 v = *(float2*)&acc[j];
        atomicAdd(lrow + 2 * j + 0, v.x);
        atomicAdd(lrow + 2 * j + 1, v.y);
    }

    // GEMM done -> help zero the output
    zero_pool((float4*)out, total4, lane);
}

// ---------------------------------------------------------------------------
// Softmax + argmax (first-max tie-break) + per-chunk ranks/histograms.
// Writes normalized gates back over g_logits, then column-sums for l_aux.
// ---------------------------------------------------------------------------
__global__ void softmax_kernel() {
    const int tid = threadIdx.x;
    const int s   = blockIdx.x * 256 + tid;
    const int lane = tid & 31;

    float x[E];
    float4* row = (float4*)(g_logits + (size_t)s * E);
#pragma unroll
    for (int j = 0; j < E / 4; ++j) {
        float4 v = row[j];
        x[4 * j + 0] = v.x; x[4 * j + 1] = v.y;
        x[4 * j + 2] = v.z; x[4 * j + 3] = v.w;
    }
    float mx = x[0];
    int am = 0;
#pragma unroll
    for (int j = 1; j < E; ++j) {
        if (x[j] > mx) { mx = x[j]; am = j; }   // strict > keeps first max
    }
    float sum = 0.f;
#pragma unroll
    for (int j = 0; j < E; ++j) sum += __expf(x[j] - mx);
    float inv = 1.f / sum;

    g_expert[s] = am;
    g_gate[s]   = inv;          // gate at argmax = exp(0)/sum

    unsigned grp = __match_any_sync(0xffffffffu, am);
    int rank = __popc(grp & ((1u << lane) - 1u));
    g_rank[s] = rank;
    if (rank == 0) g_wcount[(s >> 5) * E + am] = __popc(grp);

    // Overwrite logits row with normalized gates
#pragma unroll
    for (int j = 0; j < E / 4; ++j) {
        float4 v;
        v.x = __expf(x[4 * j + 0] - mx) * inv;
        v.y = __expf(x[4 * j + 1] - mx) * inv;
        v.z = __expf(x[4 * j + 2] - mx) * inv;
        v.w = __expf(x[4 * j + 3] - mx) * inv;
        row[j] = v;
    }
    __syncthreads();

    // Column sums of gates (for l_aux), this block's tokens only
    const int e    = tid & 63;
    const int grp2 = tid >> 6;
    const int base = blockIdx.x * 256 + grp2 * 64;
    float part = 0.f;
#pragma unroll 4
    for (int i = 0; i < 64; ++i)
        part += g_logits[(size_t)(base + i) * E + e];
    atomicAdd(&g_colsum[e], part);
}

// ---------------------------------------------------------------------------
// Per-expert exclusive prefix over the 256 chunk counts, exp_counts, l_aux.
// ---------------------------------------------------------------------------
__global__ void base_kernel(float* __restrict__ out, size_t SEC) {
    const int e = blockIdx.x;
    const int c = threadIdx.x;          // chunk 0..255
    const int lane = c & 31, w = c >> 5;

    int v = g_wcount[c * E + e];
    int x = v;
#pragma unroll
    for (int d = 1; d < 32; d <<= 1) {
        int t = __shfl_up_sync(0xffffffffu, x, d);
        if (lane >= d) x += t;
    }
    __shared__ int wsum[8];
    if (lane == 31) wsum[w] = x;
    __syncthreads();
    if (c == 0) {
        int a = 0;
#pragma unroll
        for (int i = 0; i < 8; ++i) { int t = wsum[i]; wsum[i] = a; a += t; }
    }
    __syncthreads();
    int excl = x - v + wsum[w];
    g_base[c * E + e] = excl;

    if (c == 255) {
        int tot = excl + v;
        out[1 + 2 * SEC + e] = (float)tot;        // exp_counts
        float term = g_colsum[e] * (float)tot *
                     ((float)E / ((float)S * (float)S));
        atomicAdd(out, term);                     // l_aux
    }
}

// ---------------------------------------------------------------------------
// Scatter the <= S nonzeros into the (already-zeroed) output.
// ---------------------------------------------------------------------------
__global__ void scatter_kernel(float* __restrict__ out, size_t SEC, int CAPV) {
    const int s = blockIdx.x * 256 + threadIdx.x;
    const int e = g_expert[s];
    const int pos = g_base[(s >> 5) * E + e] + g_rank[s];
    if (pos < CAPV) {
        size_t o = 1 + ((size_t)s * E + e) * (size_t)CAPV + pos;
        out[o]       = g_gate[s];   // combine_weights
        out[o + SEC] = 1.0f;        // dispatch_mask
    }
}

// ---------------------------------------------------------------------------
extern "C" void kernel_launch(void* const* d_in, const int* in_sizes, int n_in,
                              void* d_out, int out_size) {
    const float* in  = (const float*)d_in[0];
    const float* wgt = (const float*)d_in[1];
    float* out = (float*)d_out;

    // Derive capacity from out_size; fall back to the analytic value (128).
    long long c = ((long long)out_size - 1 - E) / (2LL * S * E);
    int CAPV = 128;
    if (c > 0 && (1 + 2LL * S * E * c + E) == (long long)out_size)
        CAPV = (int)c;
    size_t SEC = (size_t)S * E * (size_t)CAPV;

    init_kernel<<<128, 256>>>();
    fused_gemm_zero<<<NZERO + NCOMPUTE, 256>>>(in, wgt, out, (size_t)out_size);
    softmax_kernel<<<S / 256, 256>>>();
    base_kernel<<<E, 256>>>(out, SEC);
    scatter_kernel<<<S / 256, 256>>>(out, SEC, CAPV);
}

// round 9
// speedup vs baseline: 1.0881x; 1.0002x over previous
#include <cuda_runtime.h>
#include <cstdint>
#include <cstddef>

// Problem shape (fixed by the dataset)
#define S 8192
#define M 2048
#define E 64

#define KSPLIT 4
#define KSLICE (M / KSPLIT)      // 512
#define KC 32
#define TOKB 256                 // tokens per compute block
#define NCOMPUTE ((S / TOKB) * KSPLIT)   // 32 * 4 = 128
#define NZERO 168                // 128 + 168 = 296 = 2 * 148 SMs
#define NCHUNK (S / 32)          // 256 warp-sized token chunks

#define TILE4 4096               // float4s per zero tile (64 KB)

typedef unsigned long long u64;

// Scratch (device globals — no allocations allowed)
__device__ float    g_logits[(size_t)S * E];   // 2 MB: split-K accumulator
__device__ float    g_colsum[E];
__device__ int      g_expert[S];
__device__ float    g_gate[S];
__device__ int      g_rank[S];
__device__ int      g_wcount[NCHUNK * E];
__device__ int      g_base[NCHUNK * E];
__device__ unsigned g_ticket;

__device__ __forceinline__ u64 pack2(float x) {
    u64 r;
    asm("mov.b64 %0, {%1, %1};" : "=l"(r) : "f"(x));
    return r;
}
__device__ __forceinline__ void ffma2(u64 &d, u64 a, u64 b) {
    asm("fma.rn.f32x2 %0, %1, %2, %0;" : "+l"(d) : "l"(a), "l"(b));
}

// ---------------------------------------------------------------------------
// Warp-level work-stolen zeroing with 256-bit stores (STG.256). Each lane
// owns a 32B-aligned slice; one st.global.v8.f32 replaces two STG.128 ->
// halves MIO issue per byte.
// ---------------------------------------------------------------------------
__device__ __forceinline__ void zero_pool(float* __restrict__ out,
                                          size_t total4, int lane) {
    float4* o4 = (float4*)out;
    const float4 z4 = make_float4(0.f, 0.f, 0.f, 0.f);
    for (;;) {
        unsigned t = 0;
        if (lane == 0) t = atomicAdd(&g_ticket, 1u);
        t = __shfl_sync(0xffffffffu, t, 0);
        size_t b = (size_t)t * TILE4;
        if (b >= total4) return;
        if (b + TILE4 <= total4) {
            float* base = out + (b + (size_t)lane * 2) * 4;  // 32B aligned
#pragma unroll 8
            for (int j = 0; j < 64; ++j) {
                asm volatile(
                    "st.global.v8.f32 [%0], {%1,%1,%1,%1,%1,%1,%1,%1};"
                    :: "l"(base + (size_t)j * 256), "f"(0.f) : "memory");
            }
        } else {
            for (size_t j = b + lane; j < total4; j += 32)
                o4[j] = z4;
        }
    }
}

// ---------------------------------------------------------------------------
// init: zero split-K logits accumulator, colsum, histograms, ticket
// ---------------------------------------------------------------------------
__global__ void init_kernel() {
    int i = blockIdx.x * blockDim.x + threadIdx.x;
    float4 z = make_float4(0.f, 0.f, 0.f, 0.f);
    float4* p = (float4*)g_logits;
    const int n4 = (S * E) / 4;   // 131072
    for (int j = i; j < n4; j += gridDim.x * blockDim.x) p[j] = z;
    int4* w4 = (int4*)g_wcount;
    const int nw4 = (NCHUNK * E) / 4;  // 4096
    for (int j = i; j < nw4; j += gridDim.x * blockDim.x)
        w4[j] = make_int4(0, 0, 0, 0);
    if (i < E) g_colsum[i] = 0.f;
    if (i == 0) g_ticket = 0u;
}

// ---------------------------------------------------------------------------
// Fused kernel: bids [0, NZERO) start zeroing immediately; bids
// [NZERO, NZERO+NCOMPUTE) run the split-K GEMM, then JOIN the zeroing pool.
// 296 blocks = 2/SM, one wave.
// ---------------------------------------------------------------------------
__global__ void __launch_bounds__(256, 2)
fused_gemm_zero(const float* __restrict__ in,
                const float* __restrict__ wgt,
                float* __restrict__ out,
                size_t out_elems) {
    const int bid = blockIdx.x;
    const int tid = threadIdx.x;
    const int lane = tid & 31;
    const size_t total4 = out_elems >> 2;

    if (bid < NZERO) {
        if (bid == 0 && tid == 0) {   // tail elements (out_elems % 4)
            for (size_t r = total4 * 4; r < out_elems; ++r)
                out[r] = 0.f;
        }
        zero_pool(out, total4, lane);
        return;
    }

    // ---- compute role ----
    const int cid = bid - NZERO;
    const int tb  = cid & (S / TOKB - 1);   // token block 0..31
    const int ks  = cid / (S / TOKB);       // k-split 0..3
    const int s0  = tb * TOKB;
    const int k0  = ks * KSLICE;

    __shared__ float As[KC][TOKB + 1];   // [32][257], +1 pad
    __shared__ float Bs[KC][E];          // [32][64], read warp-uniform

    const int warp = tid >> 5;
    const int myTok = s0 + warp * 32 + lane;

    u64 acc[E / 2];
#pragma unroll
    for (int j = 0; j < E / 2; ++j) acc[j] = 0ull;

    const int a_tok = tid >> 3;   // 0..31 within a pass
    const int a_kq  = tid & 7;    // which float4 of the 32-k row

    for (int c = 0; c < KSLICE / KC; ++c) {
        const int kc = k0 + c * KC;
        // Load A chunk (256 tokens x 32 k), coalesced
#pragma unroll
        for (int p = 0; p < 8; ++p) {
            int t = p * 32 + a_tok;
            float4 v = *(const float4*)(in + (size_t)(s0 + t) * M + kc + a_kq * 4);
            As[a_kq * 4 + 0][t] = v.x;
            As[a_kq * 4 + 1][t] = v.y;
            As[a_kq * 4 + 2][t] = v.z;
            As[a_kq * 4 + 3][t] = v.w;
        }
        // Load B chunk (64 experts x 32 k)
#pragma unroll
        for (int r = 0; r < 2; ++r) {
            int q = tid * 2 + r;
            int e = q >> 3, kq = q & 7;
            float4 v = *(const float4*)(wgt + (size_t)e * M + kc + kq * 4);
            Bs[kq * 4 + 0][e] = v.x;
            Bs[kq * 4 + 1][e] = v.y;
            Bs[kq * 4 + 2][e] = v.z;
            Bs[kq * 4 + 3][e] = v.w;
        }
        __syncthreads();
#pragma unroll
        for (int kk = 0; kk < KC; ++kk) {
            float a = As[kk][tid & 255];
            u64 aa = pack2(a);
            // LDS.128 B reads: 16 MIO ops instead of 32 per k-step
            const ulonglong2* b2 = (const ulonglong2*)(&Bs[kk][0]);
#pragma unroll
            for (int j = 0; j < 16; ++j) {
                ulonglong2 bv = b2[j];
                ffma2(acc[2 * j + 0], aa, bv.x);
                ffma2(acc[2 * j + 1], aa, bv.y);
            }
        }
        __syncthreads();
    }

    // Accumulate partial logits (split-K)
    float* lrow = g_logits + (size_t)myTok * E;
#pragma unroll
    for (int j = 0; j < E / 2; ++j) {
        float2 v = *(float2*)&acc[j];
        atomicAdd(lrow + 2 * j + 0, v.x);
        atomicAdd(lrow + 2 * j + 1, v.y);
    }

    // GEMM done -> help zero the output
    zero_pool(out, total4, lane);
}

// ---------------------------------------------------------------------------
// Softmax + argmax (first-max tie-break) + per-chunk ranks/histograms.
// Writes normalized gates back over g_logits, then column-sums for l_aux.
// ---------------------------------------------------------------------------
__global__ void softmax_kernel() {
    const int tid = threadIdx.x;
    const int s   = blockIdx.x * 256 + tid;
    const int lane = tid & 31;

    float x[E];
    float4* row = (float4*)(g_logits + (size_t)s * E);
#pragma unroll
    for (int j = 0; j < E / 4; ++j) {
        float4 v = row[j];
        x[4 * j + 0] = v.x; x[4 * j + 1] = v.y;
        x[4 * j + 2] = v.z; x[4 * j + 3] = v.w;
    }
    float mx = x[0];
    int am = 0;
#pragma unroll
    for (int j = 1; j < E; ++j) {
        if (x[j] > mx) { mx = x[j]; am = j; }   // strict > keeps first max
    }
    float sum = 0.f;
#pragma unroll
    for (int j = 0; j < E; ++j) sum += __expf(x[j] - mx);
    float inv = 1.f / sum;

    g_expert[s] = am;
    g_gate[s]   = inv;          // gate at argmax = exp(0)/sum

    unsigned grp = __match_any_sync(0xffffffffu, am);
    int rank = __popc(grp & ((1u << lane) - 1u));
    g_rank[s] = rank;
    if (rank == 0) g_wcount[(s >> 5) * E + am] = __popc(grp);

    // Overwrite logits row with normalized gates
#pragma unroll
    for (int j = 0; j < E / 4; ++j) {
        float4 v;
        v.x = __expf(x[4 * j + 0] - mx) * inv;
        v.y = __expf(x[4 * j + 1] - mx) * inv;
        v.z = __expf(x[4 * j + 2] - mx) * inv;
        v.w = __expf(x[4 * j + 3] - mx) * inv;
        row[j] = v;
    }
    __syncthreads();

    // Column sums of gates (for l_aux), this block's tokens only
    const int e    = tid & 63;
    const int grp2 = tid >> 6;
    const int base = blockIdx.x * 256 + grp2 * 64;
    float part = 0.f;
#pragma unroll 4
    for (int i = 0; i < 64; ++i)
        part += g_logits[(size_t)(base + i) * E + e];
    atomicAdd(&g_colsum[e], part);
}

// ---------------------------------------------------------------------------
// Per-expert exclusive prefix over the 256 chunk counts, exp_counts, l_aux.
// ---------------------------------------------------------------------------
__global__ void base_kernel(float* __restrict__ out, size_t SEC) {
    const int e = blockIdx.x;
    const int c = threadIdx.x;          // chunk 0..255
    const int lane = c & 31, w = c >> 5;

    int v = g_wcount[c * E + e];
    int x = v;
#pragma unroll
    for (int d = 1; d < 32; d <<= 1) {
        int t = __shfl_up_sync(0xffffffffu, x, d);
        if (lane >= d) x += t;
    }
    __shared__ int wsum[8];
    if (lane == 31) wsum[w] = x;
    __syncthreads();
    if (c == 0) {
        int a = 0;
#pragma unroll
        for (int i = 0; i < 8; ++i) { int t = wsum[i]; wsum[i] = a; a += t; }
    }
    __syncthreads();
    int excl = x - v + wsum[w];
    g_base[c * E + e] = excl;

    if (c == 255) {
        int tot = excl + v;
        out[1 + 2 * SEC + e] = (float)tot;        // exp_counts
        float term = g_colsum[e] * (float)tot *
                     ((float)E / ((float)S * (float)S));
        atomicAdd(out, term);                     // l_aux
    }
}

// ---------------------------------------------------------------------------
// Scatter the <= S nonzeros into the (already-zeroed) output.
// ---------------------------------------------------------------------------
__global__ void scatter_kernel(float* __restrict__ out, size_t SEC, int CAPV) {
    const int s = blockIdx.x * 256 + threadIdx.x;
    const int e = g_expert[s];
    const int pos = g_base[(s >> 5) * E + e] + g_rank[s];
    if (pos < CAPV) {
        size_t o = 1 + ((size_t)s * E + e) * (size_t)CAPV + pos;
        out[o]       = g_gate[s];   // combine_weights
        out[o + SEC] = 1.0f;        // dispatch_mask
    }
}

// ---------------------------------------------------------------------------
extern "C" void kernel_launch(void* const* d_in, const int* in_sizes, int n_in,
                              void* d_out, int out_size) {
    const float* in  = (const float*)d_in[0];
    const float* wgt = (const float*)d_in[1];
    float* out = (float*)d_out;

    // Derive capacity from out_size; fall back to the analytic value (128).
    long long c = ((long long)out_size - 1 - E) / (2LL * S * E);
    int CAPV = 128;
    if (c > 0 && (1 + 2LL * S * E * c + E) == (long long)out_size)
        CAPV = (int)c;
    size_t SEC = (size_t)S * E * (size_t)CAPV;

    init_kernel<<<128, 256>>>();
    fused_gemm_zero<<<NZERO + NCOMPUTE, 256>>>(in, wgt, out, (size_t)out_size);
    softmax_kernel<<<S / 256, 256>>>();
    base_kernel<<<E, 256>>>(out, SEC);
    scatter_kernel<<<S / 256, 256>>>(out, SEC, CAPV);
}